// round 16
// baseline (speedup 1.0000x reference)
#include <cuda_runtime.h>
#include <cuda_bf16.h>
#include <cstdint>

// Problem constants
constexpr int B_SZ    = 2;
constexpr int S_LEN   = 2048;
constexpr int D_MODEL = 1024;
constexpr int NHEAD   = 16;
constexpr int DKH     = 64;
constexpr int NTOK    = B_SZ * S_LEN;    // 4096

// Scratch (device globals: allocation-free per harness rules)
__device__ __nv_bfloat16 g_xhi[NTOK * D_MODEL];   // X hi (also attn out hi)
__device__ __nv_bfloat16 g_xlo[NTOK * D_MODEL];
__device__ __nv_bfloat16 g_khi_in[NTOK * D_MODEL];
__device__ __nv_bfloat16 g_klo_in[NTOK * D_MODEL];
__device__ __nv_bfloat16 g_vhi_in[NTOK * D_MODEL];
__device__ __nv_bfloat16 g_vlo_in[NTOK * D_MODEL];
__device__ __nv_bfloat16 g_wqhi[D_MODEL * D_MODEL];
__device__ __nv_bfloat16 g_wqlo[D_MODEL * D_MODEL];
__device__ __nv_bfloat16 g_wkhi[D_MODEL * D_MODEL];
__device__ __nv_bfloat16 g_wklo[D_MODEL * D_MODEL];
__device__ __nv_bfloat16 g_wvhi[D_MODEL * D_MODEL];
__device__ __nv_bfloat16 g_wvlo[D_MODEL * D_MODEL];
__device__ __nv_bfloat16 g_wohi[D_MODEL * D_MODEL];
__device__ __nv_bfloat16 g_wolo[D_MODEL * D_MODEL];
__device__ __nv_bfloat16 g_qhi[NTOK * D_MODEL];
__device__ __nv_bfloat16 g_qlo[NTOK * D_MODEL];
__device__ __nv_bfloat16 g_khi[NTOK * D_MODEL];
__device__ __nv_bfloat16 g_klo[NTOK * D_MODEL];
__device__ __nv_bfloat16 g_vhi[NTOK * D_MODEL];
__device__ __nv_bfloat16 g_vlo[NTOK * D_MODEL];

// ===========================================================================
// Helpers (base-ISA only: ldmatrix / mma.sync / cp.async)
// ===========================================================================
__device__ __forceinline__ uint32_t smem_u32(const void* p) {
    uint32_t a;
    asm("{ .reg .u64 t; cvta.to.shared.u64 t, %1; cvt.u32.u64 %0, t; }"
        : "=r"(a) : "l"(p));
    return a;
}
__device__ __forceinline__ uint32_t sw64(uint32_t off) {
    return off ^ ((off >> 3) & 0x30);
}
__device__ __forceinline__ uint32_t sw128(uint32_t off) {
    return off ^ ((off >> 3) & 0x70);
}
__device__ __forceinline__ void ldm_x4(uint32_t r[4], uint32_t addr) {
    asm volatile("ldmatrix.sync.aligned.m8n8.x4.shared.b16 {%0,%1,%2,%3}, [%4];"
        : "=r"(r[0]), "=r"(r[1]), "=r"(r[2]), "=r"(r[3]) : "r"(addr));
}
__device__ __forceinline__ void ldm_x4_t(uint32_t r[4], uint32_t addr) {
    asm volatile("ldmatrix.sync.aligned.m8n8.x4.trans.shared.b16 {%0,%1,%2,%3}, [%4];"
        : "=r"(r[0]), "=r"(r[1]), "=r"(r[2]), "=r"(r[3]) : "r"(addr));
}
__device__ __forceinline__ void mma_bf16(float c[4], const uint32_t a[4],
                                         uint32_t b0, uint32_t b1) {
    asm volatile(
        "mma.sync.aligned.m16n8k16.row.col.f32.bf16.bf16.f32 "
        "{%0,%1,%2,%3}, {%4,%5,%6,%7}, {%8,%9}, {%0,%1,%2,%3};"
        : "+f"(c[0]), "+f"(c[1]), "+f"(c[2]), "+f"(c[3])
        : "r"(a[0]), "r"(a[1]), "r"(a[2]), "r"(a[3]), "r"(b0), "r"(b1));
}
__device__ __forceinline__ void cp16(uint32_t saddr, const void* gaddr) {
    asm volatile("cp.async.cg.shared.global [%0], [%1], 16;"
                 :: "r"(saddr), "l"(gaddr));
}
__device__ __forceinline__ void cp_commit() {
    asm volatile("cp.async.commit_group;" ::: "memory");
}
__device__ __forceinline__ void cp_wait0() {
    asm volatile("cp.async.wait_group 0;" ::: "memory");
}
__device__ __forceinline__ void cp_wait1() {
    asm volatile("cp.async.wait_group 1;" ::: "memory");
}
__device__ __forceinline__ float ex2(float x) {
    float y;
    asm("ex2.approx.ftz.f32 %0, %1;" : "=f"(y) : "f"(x));
    return y;
}
__device__ __forceinline__ void pack_hilo(float a, float b,
                                          uint32_t& hi, uint32_t& lo) {
    __nv_bfloat162 h = __floats2bfloat162_rn(a, b);
    float2 f = __bfloat1622float2(h);
    __nv_bfloat162 l = __floats2bfloat162_rn(a - f.x, b - f.y);
    hi = *reinterpret_cast<uint32_t*>(&h);
    lo = *reinterpret_cast<uint32_t*>(&l);
}

// ===========================================================================
// Batched fp32 -> bf16 hi/lo conversion: one launch for all 7 tensors
// ===========================================================================
struct CvtBatch {
    const float* in[7];
    __nv_bfloat16* hi[7];
    __nv_bfloat16* lo[7];
    int n4[7];
};

__global__ __launch_bounds__(256) void cvt_batch_kernel(CvtBatch cb)
{
    const int t = blockIdx.y;
    const int i = blockIdx.x * 256 + threadIdx.x;
    if (i >= cb.n4[t]) return;
    float4 v = ((const float4*)cb.in[t])[i];
    uint2 hh, ll;
    pack_hilo(v.x, v.y, hh.x, ll.x);
    pack_hilo(v.z, v.w, hh.y, ll.y);
    ((uint2*)cb.hi[t])[i] = hh;
    ((uint2*)cb.lo[t])[i] = ll;
}

// ===========================================================================
// Shared GEMM argument block
// ===========================================================================
struct GemmBatch {
    const __nv_bfloat16* Ah[3];
    const __nv_bfloat16* Al[3];
    const __nv_bfloat16* Bh[3];
    const __nv_bfloat16* Bl[3];
    const float* bias[3];
    float* Yf[3];
    __nv_bfloat16* Yh[3];
    __nv_bfloat16* Yl[3];
};

constexpr int BKC = 32;
constexpr int NC  = D_MODEL / BKC;       // 32

// ===========================================================================
// GEMM variant A (QKV, multi-wave): 64(M) x 128(N) x 32(K), 128 threads,
// 4 warps (warp tile 64x32), 2-stage pipeline, 4 CTAs/SM.  [R15-measured]
// ===========================================================================
constexpr int A_T   = 64 * BKC * 2;        // 4096
constexpr int B_T   = 128 * BKC * 2;       // 8192
constexpr int STG   = 2 * A_T + 2 * B_T;   // 24576
constexpr int GEMM_SMEM_S = 2 * STG + 1024;  // 50176

__global__ __launch_bounds__(128, 4) void gemm_bf16_s(GemmBatch gb,
                                                      int M, int N, int K)
{
    extern __shared__ char smraw[];
    const uint32_t sb = (smem_u32(smraw) + 1023) & ~1023u;
    const int z = blockIdx.z;
    const __nv_bfloat16* __restrict__ Ahi = gb.Ah[z];
    const __nv_bfloat16* __restrict__ Alo = gb.Al[z];
    const __nv_bfloat16* __restrict__ Bhi = gb.Bh[z];
    const __nv_bfloat16* __restrict__ Blo = gb.Bl[z];
    const float* __restrict__ bias = gb.bias[z];

    const int tid = threadIdx.x, lane = tid & 31, wid = tid >> 5;
    const int m0 = blockIdx.y * 64, n0 = blockIdx.x * 128;
    const int wn = wid * 32;

    auto cp_stage = [&](int c, int s) {
        const int kc = c * BKC;
        const uint32_t st = sb + s * STG;
#pragma unroll
        for (int i = 0; i < 2; ++i) {
            const int idx = i * 128 + tid;
            const int row = idx >> 2, c16 = idx & 3;
            const uint32_t so = sw64(row * 64 + c16 * 16);
            const size_t ga = (size_t)(m0 + row) * K + kc + c16 * 8;
            cp16(st + so,       Ahi + ga);
            cp16(st + A_T + so, Alo + ga);
        }
#pragma unroll
        for (int i = 0; i < 4; ++i) {
            const int idx = i * 128 + tid;
            const int row = idx >> 2, c16 = idx & 3;
            const uint32_t so = sw64(row * 64 + c16 * 16);
            const size_t gbo = (size_t)(n0 + row) * K + kc + c16 * 8;
            cp16(st + 2 * A_T + so,       Bhi + gbo);
            cp16(st + 2 * A_T + B_T + so, Blo + gbo);
        }
        cp_commit();
    };

    float acc[4][4][4];
#pragma unroll
    for (int a = 0; a < 4; ++a)
#pragma unroll
        for (int b = 0; b < 4; ++b)
#pragma unroll
            for (int d = 0; d < 4; ++d) acc[a][b][d] = 0.0f;

    cp_stage(0, 0);

    for (int c = 0; c < NC; ++c) {
        cp_wait0();
        __syncthreads();
        if (c + 1 < NC) cp_stage(c + 1, (c + 1) & 1);

        const uint32_t st = sb + (c & 1) * STG;
        const uint32_t stB = st + 2 * A_T;
#pragma unroll
        for (int ks = 0; ks < 2; ++ks) {
            uint32_t bhi[2][4], blo[2][4];
#pragma unroll
            for (int ntp = 0; ntp < 2; ++ntp) {
                const uint32_t off = sw64((wn + ntp * 16 + ((lane >> 4) << 3) +
                                           (lane & 7)) * 64 +
                                          ks * 32 + ((lane >> 3) & 1) * 16);
                ldm_x4(bhi[ntp], stB + off);
                ldm_x4(blo[ntp], stB + B_T + off);
            }
#pragma unroll
            for (int mt = 0; mt < 4; ++mt) {
                uint32_t ahi[4], alo[4];
                const uint32_t off = sw64((mt * 16 + (lane & 15)) * 64 +
                                          ks * 32 + (lane >> 4) * 16);
                ldm_x4(ahi, st + off);
                ldm_x4(alo, st + A_T + off);
#pragma unroll
                for (int nt = 0; nt < 4; ++nt) {
                    const int p = nt >> 1, q = (nt & 1) * 2;
                    mma_bf16(acc[mt][nt], ahi, bhi[p][q], bhi[p][q + 1]);
                    mma_bf16(acc[mt][nt], ahi, blo[p][q], blo[p][q + 1]);
                    mma_bf16(acc[mt][nt], alo, bhi[p][q], bhi[p][q + 1]);
                }
            }
        }
        __syncthreads();
    }

    // Epilogue (bf16 hi/lo or fp32)
    if (gb.Yf[z]) {
        float* __restrict__ Y = gb.Yf[z];
#pragma unroll
        for (int mt = 0; mt < 4; ++mt) {
            const int row = m0 + mt * 16 + (lane >> 2);
#pragma unroll
            for (int nt = 0; nt < 4; ++nt) {
                const int col = n0 + wn + nt * 8 + (lane & 3) * 2;
                const float b0v = __ldg(&bias[col]);
                const float b1v = __ldg(&bias[col + 1]);
                *(float2*)(Y + (size_t)row * N + col) =
                    make_float2(acc[mt][nt][0] + b0v, acc[mt][nt][1] + b1v);
                *(float2*)(Y + (size_t)(row + 8) * N + col) =
                    make_float2(acc[mt][nt][2] + b0v, acc[mt][nt][3] + b1v);
            }
        }
    } else {
        __nv_bfloat16* __restrict__ Yh = gb.Yh[z];
        __nv_bfloat16* __restrict__ Yl = gb.Yl[z];
#pragma unroll
        for (int mt = 0; mt < 4; ++mt) {
            const int row = m0 + mt * 16 + (lane >> 2);
#pragma unroll
            for (int nt = 0; nt < 4; ++nt) {
                const int col = n0 + wn + nt * 8 + (lane & 3) * 2;
                const float b0v = __ldg(&bias[col]);
                const float b1v = __ldg(&bias[col + 1]);
                uint32_t hh, ll;
                pack_hilo(acc[mt][nt][0] + b0v, acc[mt][nt][1] + b1v, hh, ll);
                *(uint32_t*)(Yh + (size_t)row * N + col) = hh;
                *(uint32_t*)(Yl + (size_t)row * N + col) = ll;
                pack_hilo(acc[mt][nt][2] + b0v, acc[mt][nt][3] + b1v, hh, ll);
                *(uint32_t*)(Yh + (size_t)(row + 8) * N + col) = hh;
                *(uint32_t*)(Yl + (size_t)(row + 8) * N + col) = ll;
            }
        }
    }
}

// ===========================================================================
// GEMM variant B (O-projection, single-wave): 128x128x32, 256 threads,
// 8 warps (2Mx4N), 3-stage pipeline, single barrier/chunk.  [R12-measured]
// ===========================================================================
constexpr int TILE8K = 128 * BKC * 2;       // 8192
constexpr int STAGE_BYTES = 4 * TILE8K;     // 32768
constexpr int GEMM_SMEM_L = 3 * STAGE_BYTES + 1024;   // 99328

__global__ __launch_bounds__(256, 2) void gemm_bf16_l(GemmBatch gb,
                                                      int M, int N, int K)
{
    extern __shared__ char smraw[];
    const uint32_t sb = (smem_u32(smraw) + 1023) & ~1023u;
    const int z = blockIdx.z;
    const __nv_bfloat16* __restrict__ Ahi = gb.Ah[z];
    const __nv_bfloat16* __restrict__ Alo = gb.Al[z];
    const __nv_bfloat16* __restrict__ Bhi = gb.Bh[z];
    const __nv_bfloat16* __restrict__ Blo = gb.Bl[z];
    const float* __restrict__ bias = gb.bias[z];

    const int tid = threadIdx.x, lane = tid & 31, wid = tid >> 5;
    const int m0 = blockIdx.y * 128, n0 = blockIdx.x * 128;
    const int wm = (wid >> 2) * 64;
    const int wn = (wid & 3) * 32;

    const int lrow = tid >> 2;
    const int c16  = tid & 3;

    auto cp_stage = [&](int c, int s) {
        const int kc = c * BKC;
        const uint32_t st = sb + s * STAGE_BYTES;
#pragma unroll
        for (int i = 0; i < 2; ++i) {
            const int row = i * 64 + lrow;
            const uint32_t so = sw64(row * 64 + c16 * 16);
            const size_t ga = (size_t)(m0 + row) * K + kc + c16 * 8;
            const size_t gbo = (size_t)(n0 + row) * K + kc + c16 * 8;
            cp16(st + so,              Ahi + ga);
            cp16(st + TILE8K + so,     Alo + ga);
            cp16(st + 2 * TILE8K + so, Bhi + gbo);
            cp16(st + 3 * TILE8K + so, Blo + gbo);
        }
        cp_commit();
    };

    float acc[4][4][4];
#pragma unroll
    for (int a = 0; a < 4; ++a)
#pragma unroll
        for (int b = 0; b < 4; ++b)
#pragma unroll
            for (int d = 0; d < 4; ++d) acc[a][b][d] = 0.0f;

    cp_stage(0, 0);
    cp_stage(1, 1);

    int sr = 0, sw = 2;

    for (int c = 0; c < NC; ++c) {
        cp_wait1();
        __syncthreads();
        if (c + 2 < NC) cp_stage(c + 2, sw);
        else            cp_commit();

        const uint32_t st = sb + sr * STAGE_BYTES;
#pragma unroll
        for (int ks = 0; ks < 2; ++ks) {
            uint32_t bhi[2][4], blo[2][4];
#pragma unroll
            for (int ntp = 0; ntp < 2; ++ntp) {
                const uint32_t off = sw64((wn + ntp * 16 + ((lane >> 4) << 3) +
                                           (lane & 7)) * 64 +
                                          ks * 32 + ((lane >> 3) & 1) * 16);
                ldm_x4(bhi[ntp], st + 2 * TILE8K + off);
                ldm_x4(blo[ntp], st + 3 * TILE8K + off);
            }
#pragma unroll
            for (int mt = 0; mt < 4; ++mt) {
                uint32_t ahi[4], alo[4];
                const uint32_t off = sw64((wm + mt * 16 + (lane & 15)) * 64 +
                                          ks * 32 + (lane >> 4) * 16);
                ldm_x4(ahi, st + off);
                ldm_x4(alo, st + TILE8K + off);
#pragma unroll
                for (int nt = 0; nt < 4; ++nt) {
                    const int p = nt >> 1, q = (nt & 1) * 2;
                    mma_bf16(acc[mt][nt], ahi, bhi[p][q], bhi[p][q + 1]);
                    mma_bf16(acc[mt][nt], ahi, blo[p][q], blo[p][q + 1]);
                    mma_bf16(acc[mt][nt], alo, bhi[p][q], bhi[p][q + 1]);
                }
            }
        }
        sr = (sr == 2) ? 0 : sr + 1;
        sw = (sw == 2) ? 0 : sw + 1;
    }

    // Epilogue
    if (gb.Yf[z]) {
        float* __restrict__ Y = gb.Yf[z];
#pragma unroll
        for (int mt = 0; mt < 4; ++mt) {
            const int row = m0 + wm + mt * 16 + (lane >> 2);
#pragma unroll
            for (int nt = 0; nt < 4; ++nt) {
                const int col = n0 + wn + nt * 8 + (lane & 3) * 2;
                const float b0v = __ldg(&bias[col]);
                const float b1v = __ldg(&bias[col + 1]);
                *(float2*)(Y + (size_t)row * N + col) =
                    make_float2(acc[mt][nt][0] + b0v, acc[mt][nt][1] + b1v);
                *(float2*)(Y + (size_t)(row + 8) * N + col) =
                    make_float2(acc[mt][nt][2] + b0v, acc[mt][nt][3] + b1v);
            }
        }
    } else {
        __nv_bfloat16* __restrict__ Yh = gb.Yh[z];
        __nv_bfloat16* __restrict__ Yl = gb.Yl[z];
#pragma unroll
        for (int mt = 0; mt < 4; ++mt) {
            const int row = m0 + wm + mt * 16 + (lane >> 2);
#pragma unroll
            for (int nt = 0; nt < 4; ++nt) {
                const int col = n0 + wn + nt * 8 + (lane & 3) * 2;
                const float b0v = __ldg(&bias[col]);
                const float b1v = __ldg(&bias[col + 1]);
                uint32_t hh, ll;
                pack_hilo(acc[mt][nt][0] + b0v, acc[mt][nt][1] + b1v, hh, ll);
                *(uint32_t*)(Yh + (size_t)row * N + col) = hh;
                *(uint32_t*)(Yl + (size_t)row * N + col) = ll;
                pack_hilo(acc[mt][nt][2] + b0v, acc[mt][nt][3] + b1v, hh, ll);
                *(uint32_t*)(Yh + (size_t)(row + 8) * N + col) = hh;
                *(uint32_t*)(Yl + (size_t)(row + 8) * N + col) = ll;
            }
        }
    }
}

// ===========================================================================
// Tensor-core flash attention — R13-validated: 64q/128thr, 2-stage KV,
// Q fragments loaded directly from global, 3 CTAs/SM.
// ===========================================================================
constexpr int ATT_SMEM = 1024 + 2 * 32768;   // 66560

__global__ __launch_bounds__(128, 3) void attn_tc(
    const __nv_bfloat16* __restrict__ qh_, const __nv_bfloat16* __restrict__ ql_,
    const __nv_bfloat16* __restrict__ kh_, const __nv_bfloat16* __restrict__ kl_,
    const __nv_bfloat16* __restrict__ vh_, const __nv_bfloat16* __restrict__ vl_,
    __nv_bfloat16* __restrict__ ohi, __nv_bfloat16* __restrict__ olo)
{
    extern __shared__ char smraw[];
    const uint32_t sb = (smem_u32(smraw) + 1023) & ~1023u;
    const int tid = threadIdx.x, lane = tid & 31, wid = tid >> 5;
    const int qt = blockIdx.x, h = blockIdx.y, b = blockIdx.z;
    const size_t bt = (size_t)b * S_LEN;

    auto cp_kv = [&](int kt, int s) {
        const uint32_t st = sb + s * 32768;
        const int row = tid >> 3, c = tid & 7;
        const size_t g0 = (bt + (size_t)kt * 64) * D_MODEL + h * DKH + c * 8;
#pragma unroll
        for (int it = 0; it < 4; ++it) {
            const int r = it * 16 + row;
            const uint32_t so = sw128(r * 128 + c * 16);
            const size_t g = g0 + (size_t)r * D_MODEL;
            cp16(st + so,         kh_ + g);
            cp16(st + 8192 + so,  kl_ + g);
            cp16(st + 16384 + so, vh_ + g);
            cp16(st + 24576 + so, vl_ + g);
        }
        cp_commit();
    };

    cp_kv(0, 0);
    cp_kv(1, 1);

    // ---- Q fragments: direct global loads in MMA A-fragment layout ----
    uint32_t qfh[4][4], qfl[4][4];
    {
        const int qrow = qt * 64 + wid * 16 + (lane >> 2);
        const size_t base = (bt + qrow) * D_MODEL + h * DKH + (lane & 3) * 2;
        const size_t base8 = base + (size_t)8 * D_MODEL;
#pragma unroll
        for (int ks = 0; ks < 4; ++ks) {
            const int kofs = ks * 16;
            qfh[ks][0] = *(const uint32_t*)(qh_ + base  + kofs);
            qfh[ks][1] = *(const uint32_t*)(qh_ + base8 + kofs);
            qfh[ks][2] = *(const uint32_t*)(qh_ + base  + kofs + 8);
            qfh[ks][3] = *(const uint32_t*)(qh_ + base8 + kofs + 8);
            qfl[ks][0] = *(const uint32_t*)(ql_ + base  + kofs);
            qfl[ks][1] = *(const uint32_t*)(ql_ + base8 + kofs);
            qfl[ks][2] = *(const uint32_t*)(ql_ + base  + kofs + 8);
            qfl[ks][3] = *(const uint32_t*)(ql_ + base8 + kofs + 8);
        }
    }

    float s[8][4], out[8][4];
    float m0 = -1e30f, m1 = -1e30f, l0 = 0.0f, l1 = 0.0f;
#pragma unroll
    for (int nt = 0; nt < 8; ++nt)
#pragma unroll
        for (int v = 0; v < 4; ++v) out[nt][v] = 0.0f;

    constexpr float SC = 0.18033688f;   // 0.125 * log2(e)

    for (int kt = 0; kt < S_LEN / 64; ++kt) {
        cp_wait1();
        __syncthreads();

        const uint32_t KH = sb + (kt & 1) * 32768;
        const uint32_t KL = KH + 8192, VH = KH + 16384, VL = KH + 24576;

        // ---- scores S = Q.K^T (hi/lo 3-MMA) ----
#pragma unroll
        for (int nt = 0; nt < 8; ++nt)
#pragma unroll
            for (int v = 0; v < 4; ++v) s[nt][v] = 0.0f;

#pragma unroll
        for (int ntp = 0; ntp < 4; ++ntp) {
            const uint32_t rb = (ntp * 16 + ((lane >> 4) << 3) + (lane & 7)) * 128;
#pragma unroll
            for (int ks = 0; ks < 4; ++ks) {
                const uint32_t off = sw128(rb + ks * 32 + ((lane >> 3) & 1) * 16);
                uint32_t bh[4], bl[4];
                ldm_x4(bh, KH + off);
                ldm_x4(bl, KL + off);
                mma_bf16(s[2 * ntp],     qfh[ks], bh[0], bh[1]);
                mma_bf16(s[2 * ntp],     qfh[ks], bl[0], bl[1]);
                mma_bf16(s[2 * ntp],     qfl[ks], bh[0], bh[1]);
                mma_bf16(s[2 * ntp + 1], qfh[ks], bh[2], bh[3]);
                mma_bf16(s[2 * ntp + 1], qfh[ks], bl[2], bl[3]);
                mma_bf16(s[2 * ntp + 1], qfl[ks], bh[2], bh[3]);
            }
        }

        // ---- online softmax (exp2 domain) ----
        float mx0 = -1e30f, mx1 = -1e30f;
#pragma unroll
        for (int nt = 0; nt < 8; ++nt) {
            s[nt][0] *= SC; s[nt][1] *= SC; s[nt][2] *= SC; s[nt][3] *= SC;
            mx0 = fmaxf(mx0, fmaxf(s[nt][0], s[nt][1]));
            mx1 = fmaxf(mx1, fmaxf(s[nt][2], s[nt][3]));
        }
        mx0 = fmaxf(mx0, __shfl_xor_sync(0xffffffffu, mx0, 1));
        mx0 = fmaxf(mx0, __shfl_xor_sync(0xffffffffu, mx0, 2));
        mx1 = fmaxf(mx1, __shfl_xor_sync(0xffffffffu, mx1, 1));
        mx1 = fmaxf(mx1, __shfl_xor_sync(0xffffffffu, mx1, 2));
        const float nm0 = fmaxf(m0, mx0), nm1 = fmaxf(m1, mx1);
        const float a0 = ex2(m0 - nm0), a1 = ex2(m1 - nm1);
        m0 = nm0; m1 = nm1;
        float rs0 = 0.0f, rs1 = 0.0f;
#pragma unroll
        for (int nt = 0; nt < 8; ++nt) {
            s[nt][0] = ex2(s[nt][0] - m0);
            s[nt][1] = ex2(s[nt][1] - m0);
            s[nt][2] = ex2(s[nt][2] - m1);
            s[nt][3] = ex2(s[nt][3] - m1);
            rs0 += s[nt][0] + s[nt][1];
            rs1 += s[nt][2] + s[nt][3];
            out[nt][0] *= a0; out[nt][1] *= a0;
            out[nt][2] *= a1; out[nt][3] *= a1;
        }
        rs0 += __shfl_xor_sync(0xffffffffu, rs0, 1);
        rs0 += __shfl_xor_sync(0xffffffffu, rs0, 2);
        rs1 += __shfl_xor_sync(0xffffffffu, rs1, 1);
        rs1 += __shfl_xor_sync(0xffffffffu, rs1, 2);
        l0 = l0 * a0 + rs0;
        l1 = l1 * a1 + rs1;

        // ---- PV: out += P.V ----
#pragma unroll
        for (int ks = 0; ks < 4; ++ks) {
            uint32_t ph[4], pl[4];
            pack_hilo(s[2 * ks][0],     s[2 * ks][1],     ph[0], pl[0]);
            pack_hilo(s[2 * ks][2],     s[2 * ks][3],     ph[1], pl[1]);
            pack_hilo(s[2 * ks + 1][0], s[2 * ks + 1][1], ph[2], pl[2]);
            pack_hilo(s[2 * ks + 1][2], s[2 * ks + 1][3], ph[3], pl[3]);
            const uint32_t vrow = (ks * 16 + ((lane >> 3) & 1) * 8 + (lane & 7)) * 128;
#pragma unroll
            for (int np = 0; np < 4; ++np) {
                const uint32_t off = sw128(vrow + np * 32 + (lane >> 4) * 16);
                uint32_t vh4[4], vl4[4];
                ldm_x4_t(vh4, VH + off);
                ldm_x4_t(vl4, VL + off);
                mma_bf16(out[2 * np],     ph, vh4[0], vh4[1]);
                mma_bf16(out[2 * np],     ph, vl4[0], vl4[1]);
                mma_bf16(out[2 * np],     pl, vh4[0], vh4[1]);
                mma_bf16(out[2 * np + 1], ph, vh4[2], vh4[3]);
                mma_bf16(out[2 * np + 1], ph, vl4[2], vl4[3]);
                mma_bf16(out[2 * np + 1], pl, vh4[2], vh4[3]);
            }
        }

        __syncthreads();
        if (kt + 2 < S_LEN / 64) cp_kv(kt + 2, kt & 1);
        else cp_commit();
    }

    // ---- epilogue: normalize, emit bf16 hi/lo for the O-projection ----
    const float i0 = 1.0f / l0, i1 = 1.0f / l1;
    const int r0 = qt * 64 + wid * 16 + (lane >> 2);
    const size_t t0 = (bt + r0) * D_MODEL;
    const size_t t1 = t0 + 8 * D_MODEL;
#pragma unroll
    for (int nt = 0; nt < 8; ++nt) {
        const int col = h * DKH + nt * 8 + (lane & 3) * 2;
        uint32_t hh, ll;
        pack_hilo(out[nt][0] * i0, out[nt][1] * i0, hh, ll);
        *(uint32_t*)(ohi + t0 + col) = hh;
        *(uint32_t*)(olo + t0 + col) = ll;
        pack_hilo(out[nt][2] * i1, out[nt][3] * i1, hh, ll);
        *(uint32_t*)(ohi + t1 + col) = hh;
        *(uint32_t*)(olo + t1 + col) = ll;
    }
}

// ===========================================================================
// kernel_launch: Q K V Wq bq Wk bk Wv bv Wo bo ; output float32
// ===========================================================================
extern "C" void kernel_launch(void* const* d_in, const int* in_sizes, int n_in,
                              void* d_out, int out_size)
{
    const float* Q  = (const float*)d_in[0];
    const float* K  = (const float*)d_in[1];
    const float* V  = (const float*)d_in[2];
    const float* Wq = (const float*)d_in[3];
    const float* bq = (const float*)d_in[4];
    const float* Wk = (const float*)d_in[5];
    const float* bk = (const float*)d_in[6];
    const float* Wv = (const float*)d_in[7];
    const float* bv = (const float*)d_in[8];
    const float* Wo = (const float*)d_in[9];
    const float* bo = (const float*)d_in[10];
    float* out = (float*)d_out;

    __nv_bfloat16 *xhi, *xlo, *kih, *kil, *vih, *vil;
    __nv_bfloat16 *wqh, *wql, *wkh, *wkl, *wvh, *wvl, *woh, *wol;
    __nv_bfloat16 *qhi, *qlo, *khi, *klo, *vhi, *vlo;
    cudaGetSymbolAddress((void**)&xhi, g_xhi);
    cudaGetSymbolAddress((void**)&xlo, g_xlo);
    cudaGetSymbolAddress((void**)&kih, g_khi_in);
    cudaGetSymbolAddress((void**)&kil, g_klo_in);
    cudaGetSymbolAddress((void**)&vih, g_vhi_in);
    cudaGetSymbolAddress((void**)&vil, g_vlo_in);
    cudaGetSymbolAddress((void**)&wqh, g_wqhi);
    cudaGetSymbolAddress((void**)&wql, g_wqlo);
    cudaGetSymbolAddress((void**)&wkh, g_wkhi);
    cudaGetSymbolAddress((void**)&wkl, g_wklo);
    cudaGetSymbolAddress((void**)&wvh, g_wvhi);
    cudaGetSymbolAddress((void**)&wvl, g_wvlo);
    cudaGetSymbolAddress((void**)&woh, g_wohi);
    cudaGetSymbolAddress((void**)&wol, g_wolo);
    cudaGetSymbolAddress((void**)&qhi, g_qhi);
    cudaGetSymbolAddress((void**)&qlo, g_qlo);
    cudaGetSymbolAddress((void**)&khi, g_khi);
    cudaGetSymbolAddress((void**)&klo, g_klo);
    cudaGetSymbolAddress((void**)&vhi, g_vhi);
    cudaGetSymbolAddress((void**)&vlo, g_vlo);

    cudaFuncSetAttribute(gemm_bf16_s,
                         cudaFuncAttributeMaxDynamicSharedMemorySize, GEMM_SMEM_S);
    cudaFuncSetAttribute(gemm_bf16_l,
                         cudaFuncAttributeMaxDynamicSharedMemorySize, GEMM_SMEM_L);
    cudaFuncSetAttribute(attn_tc,
                         cudaFuncAttributeMaxDynamicSharedMemorySize, ATT_SMEM);

    const int nX4 = NTOK * D_MODEL / 4;      // 1,048,576
    const int nW4 = D_MODEL * D_MODEL / 4;   // 262,144

    // --- single batched conversion: Q, K, V inputs + 4 weights ---
    CvtBatch cb;
    cb.in[0] = Q;  cb.hi[0] = xhi; cb.lo[0] = xlo; cb.n4[0] = nX4;
    cb.in[1] = K;  cb.hi[1] = kih; cb.lo[1] = kil; cb.n4[1] = nX4;
    cb.in[2] = V;  cb.hi[2] = vih; cb.lo[2] = vil; cb.n4[2] = nX4;
    cb.in[3] = Wq; cb.hi[3] = wqh; cb.lo[3] = wql; cb.n4[3] = nW4;
    cb.in[4] = Wk; cb.hi[4] = wkh; cb.lo[4] = wkl; cb.n4[4] = nW4;
    cb.in[5] = Wv; cb.hi[5] = wvh; cb.lo[5] = wvl; cb.n4[5] = nW4;
    cb.in[6] = Wo; cb.hi[6] = woh; cb.lo[6] = wol; cb.n4[6] = nW4;
    cvt_batch_kernel<<<dim3(nX4 / 256, 7), 256>>>(cb);

    // --- fused QKV projections: small-tile variant (multi-wave optimal) ---
    GemmBatch gq;
    gq.Ah[0] = xhi; gq.Al[0] = xlo; gq.Bh[0] = wqh; gq.Bl[0] = wql;
    gq.bias[0] = bq; gq.Yf[0] = nullptr; gq.Yh[0] = qhi; gq.Yl[0] = qlo;
    gq.Ah[1] = kih; gq.Al[1] = kil; gq.Bh[1] = wkh; gq.Bl[1] = wkl;
    gq.bias[1] = bk; gq.Yf[1] = nullptr; gq.Yh[1] = khi; gq.Yl[1] = klo;
    gq.Ah[2] = vih; gq.Al[2] = vil; gq.Bh[2] = wvh; gq.Bl[2] = wvl;
    gq.bias[2] = bv; gq.Yf[2] = nullptr; gq.Yh[2] = vhi; gq.Yl[2] = vlo;
    dim3 ggrid(D_MODEL / 128, NTOK / 64, 3);     // (8, 64, 3)
    gemm_bf16_s<<<ggrid, 128, GEMM_SMEM_S>>>(gq, NTOK, D_MODEL, D_MODEL);

    // --- attention: 64-query CTAs, 3 CTAs/SM ---
    dim3 agrid(S_LEN / 64, NHEAD, B_SZ);         // (32, 16, 2)
    attn_tc<<<agrid, 128, ATT_SMEM>>>(qhi, qlo, khi, klo, vhi, vlo, xhi, xlo);

    // --- output projection: large-tile variant (single-wave optimal) ---
    GemmBatch go;
    go.Ah[0] = xhi; go.Al[0] = xlo; go.Bh[0] = woh; go.Bl[0] = wol;
    go.bias[0] = bo; go.Yf[0] = out; go.Yh[0] = nullptr; go.Yl[0] = nullptr;
    go.Ah[1] = go.Ah[2] = xhi; go.Al[1] = go.Al[2] = xlo;
    go.Bh[1] = go.Bh[2] = woh; go.Bl[1] = go.Bl[2] = wol;
    go.bias[1] = go.bias[2] = bo;
    go.Yf[1] = go.Yf[2] = out;
    go.Yh[1] = go.Yh[2] = nullptr; go.Yl[1] = go.Yl[2] = nullptr;
    dim3 ogrid(D_MODEL / 128, NTOK / 128, 1);    // (8, 32, 1)
    gemm_bf16_l<<<ogrid, 256, GEMM_SMEM_L>>>(go, NTOK, D_MODEL, D_MODEL);
}

// round 17
// speedup vs baseline: 1.0114x; 1.0114x over previous
#include <cuda_runtime.h>
#include <cuda_bf16.h>
#include <cstdint>

// Problem constants
constexpr int B_SZ    = 2;
constexpr int S_LEN   = 2048;
constexpr int D_MODEL = 1024;
constexpr int NHEAD   = 16;
constexpr int DKH     = 64;
constexpr int NTOK    = B_SZ * S_LEN;    // 4096

// Scratch (device globals: allocation-free per harness rules)
__device__ __nv_bfloat16 g_xhi[NTOK * D_MODEL];   // X hi (also attn out hi)
__device__ __nv_bfloat16 g_xlo[NTOK * D_MODEL];
__device__ __nv_bfloat16 g_khi_in[NTOK * D_MODEL];
__device__ __nv_bfloat16 g_klo_in[NTOK * D_MODEL];
__device__ __nv_bfloat16 g_vhi_in[NTOK * D_MODEL];
__device__ __nv_bfloat16 g_vlo_in[NTOK * D_MODEL];
__device__ __nv_bfloat16 g_wqhi[D_MODEL * D_MODEL];
__device__ __nv_bfloat16 g_wqlo[D_MODEL * D_MODEL];
__device__ __nv_bfloat16 g_wkhi[D_MODEL * D_MODEL];
__device__ __nv_bfloat16 g_wklo[D_MODEL * D_MODEL];
__device__ __nv_bfloat16 g_wvhi[D_MODEL * D_MODEL];
__device__ __nv_bfloat16 g_wvlo[D_MODEL * D_MODEL];
__device__ __nv_bfloat16 g_wohi[D_MODEL * D_MODEL];
__device__ __nv_bfloat16 g_wolo[D_MODEL * D_MODEL];
__device__ __nv_bfloat16 g_qhi[NTOK * D_MODEL];
__device__ __nv_bfloat16 g_qlo[NTOK * D_MODEL];
__device__ __nv_bfloat16 g_khi[NTOK * D_MODEL];
__device__ __nv_bfloat16 g_klo[NTOK * D_MODEL];
__device__ __nv_bfloat16 g_vhi[NTOK * D_MODEL];
__device__ __nv_bfloat16 g_vlo[NTOK * D_MODEL];

// ===========================================================================
// Helpers (base-ISA only: ldmatrix / mma.sync / cp.async)
// ===========================================================================
__device__ __forceinline__ uint32_t smem_u32(const void* p) {
    uint32_t a;
    asm("{ .reg .u64 t; cvta.to.shared.u64 t, %1; cvt.u32.u64 %0, t; }"
        : "=r"(a) : "l"(p));
    return a;
}
__device__ __forceinline__ uint32_t sw64(uint32_t off) {
    return off ^ ((off >> 3) & 0x30);
}
__device__ __forceinline__ uint32_t sw128(uint32_t off) {
    return off ^ ((off >> 3) & 0x70);
}
__device__ __forceinline__ void ldm_x4(uint32_t r[4], uint32_t addr) {
    asm volatile("ldmatrix.sync.aligned.m8n8.x4.shared.b16 {%0,%1,%2,%3}, [%4];"
        : "=r"(r[0]), "=r"(r[1]), "=r"(r[2]), "=r"(r[3]) : "r"(addr));
}
__device__ __forceinline__ void ldm_x4_t(uint32_t r[4], uint32_t addr) {
    asm volatile("ldmatrix.sync.aligned.m8n8.x4.trans.shared.b16 {%0,%1,%2,%3}, [%4];"
        : "=r"(r[0]), "=r"(r[1]), "=r"(r[2]), "=r"(r[3]) : "r"(addr));
}
__device__ __forceinline__ void mma_bf16(float c[4], const uint32_t a[4],
                                         uint32_t b0, uint32_t b1) {
    asm volatile(
        "mma.sync.aligned.m16n8k16.row.col.f32.bf16.bf16.f32 "
        "{%0,%1,%2,%3}, {%4,%5,%6,%7}, {%8,%9}, {%0,%1,%2,%3};"
        : "+f"(c[0]), "+f"(c[1]), "+f"(c[2]), "+f"(c[3])
        : "r"(a[0]), "r"(a[1]), "r"(a[2]), "r"(a[3]), "r"(b0), "r"(b1));
}
__device__ __forceinline__ void cp16(uint32_t saddr, const void* gaddr) {
    asm volatile("cp.async.cg.shared.global [%0], [%1], 16;"
                 :: "r"(saddr), "l"(gaddr));
}
__device__ __forceinline__ void cp_commit() {
    asm volatile("cp.async.commit_group;" ::: "memory");
}
__device__ __forceinline__ void cp_wait0() {
    asm volatile("cp.async.wait_group 0;" ::: "memory");
}
__device__ __forceinline__ void cp_wait1() {
    asm volatile("cp.async.wait_group 1;" ::: "memory");
}
__device__ __forceinline__ float ex2(float x) {
    float y;
    asm("ex2.approx.ftz.f32 %0, %1;" : "=f"(y) : "f"(x));
    return y;
}
__device__ __forceinline__ void pack_hilo(float a, float b,
                                          uint32_t& hi, uint32_t& lo) {
    __nv_bfloat162 h = __floats2bfloat162_rn(a, b);
    float2 f = __bfloat1622float2(h);
    __nv_bfloat162 l = __floats2bfloat162_rn(a - f.x, b - f.y);
    hi = *reinterpret_cast<uint32_t*>(&h);
    lo = *reinterpret_cast<uint32_t*>(&l);
}

// ===========================================================================
// Batched fp32 -> bf16 hi/lo conversion, MLP=4: each thread issues 4
// independent float4 loads (coalesced within the block's 1024-elem span),
// then converts and stores 4 independent uint2 pairs. Same per-element
// rounding ops as before -> bit-identical outputs.
// ===========================================================================
struct CvtBatch {
    const float* in[7];
    __nv_bfloat16* hi[7];
    __nv_bfloat16* lo[7];
    int n4[7];
};

__global__ __launch_bounds__(256) void cvt_batch_kernel(CvtBatch cb)
{
    const int t = blockIdx.y;
    const int n4 = cb.n4[t];
    const int base = blockIdx.x * 1024 + threadIdx.x;
    if (base >= n4) return;

    const float4* __restrict__ in = (const float4*)cb.in[t];
    uint2* __restrict__ ho = (uint2*)cb.hi[t];
    uint2* __restrict__ lo = (uint2*)cb.lo[t];

    float4 v[4];
    int   idx[4];
    int   cnt = 0;
#pragma unroll
    for (int j = 0; j < 4; ++j) {
        const int i = base + j * 256;
        if (i < n4) { idx[cnt] = i; v[cnt] = in[i]; ++cnt; }
    }
#pragma unroll
    for (int j = 0; j < 4; ++j) {
        if (j < cnt) {
            uint2 hh, ll;
            pack_hilo(v[j].x, v[j].y, hh.x, ll.x);
            pack_hilo(v[j].z, v[j].w, hh.y, ll.y);
            ho[idx[j]] = hh;
            lo[idx[j]] = ll;
        }
    }
}

// ===========================================================================
// Shared GEMM argument block
// ===========================================================================
struct GemmBatch {
    const __nv_bfloat16* Ah[3];
    const __nv_bfloat16* Al[3];
    const __nv_bfloat16* Bh[3];
    const __nv_bfloat16* Bl[3];
    const float* bias[3];
    float* Yf[3];
    __nv_bfloat16* Yh[3];
    __nv_bfloat16* Yl[3];
};

constexpr int BKC = 32;
constexpr int NC  = D_MODEL / BKC;       // 32

// ===========================================================================
// GEMM variant A (QKV, multi-wave): 64(M) x 128(N) x 32(K), 128 threads,
// 4 warps (warp tile 64x32), 2-stage pipeline, 4 CTAs/SM.  [R15-measured]
// ===========================================================================
constexpr int A_T   = 64 * BKC * 2;        // 4096
constexpr int B_T   = 128 * BKC * 2;       // 8192
constexpr int STG   = 2 * A_T + 2 * B_T;   // 24576
constexpr int GEMM_SMEM_S = 2 * STG + 1024;  // 50176

__global__ __launch_bounds__(128, 4) void gemm_bf16_s(GemmBatch gb,
                                                      int M, int N, int K)
{
    extern __shared__ char smraw[];
    const uint32_t sb = (smem_u32(smraw) + 1023) & ~1023u;
    const int z = blockIdx.z;
    const __nv_bfloat16* __restrict__ Ahi = gb.Ah[z];
    const __nv_bfloat16* __restrict__ Alo = gb.Al[z];
    const __nv_bfloat16* __restrict__ Bhi = gb.Bh[z];
    const __nv_bfloat16* __restrict__ Blo = gb.Bl[z];
    const float* __restrict__ bias = gb.bias[z];

    const int tid = threadIdx.x, lane = tid & 31, wid = tid >> 5;
    const int m0 = blockIdx.y * 64, n0 = blockIdx.x * 128;
    const int wn = wid * 32;

    auto cp_stage = [&](int c, int s) {
        const int kc = c * BKC;
        const uint32_t st = sb + s * STG;
#pragma unroll
        for (int i = 0; i < 2; ++i) {
            const int idx = i * 128 + tid;
            const int row = idx >> 2, c16 = idx & 3;
            const uint32_t so = sw64(row * 64 + c16 * 16);
            const size_t ga = (size_t)(m0 + row) * K + kc + c16 * 8;
            cp16(st + so,       Ahi + ga);
            cp16(st + A_T + so, Alo + ga);
        }
#pragma unroll
        for (int i = 0; i < 4; ++i) {
            const int idx = i * 128 + tid;
            const int row = idx >> 2, c16 = idx & 3;
            const uint32_t so = sw64(row * 64 + c16 * 16);
            const size_t gbo = (size_t)(n0 + row) * K + kc + c16 * 8;
            cp16(st + 2 * A_T + so,       Bhi + gbo);
            cp16(st + 2 * A_T + B_T + so, Blo + gbo);
        }
        cp_commit();
    };

    float acc[4][4][4];
#pragma unroll
    for (int a = 0; a < 4; ++a)
#pragma unroll
        for (int b = 0; b < 4; ++b)
#pragma unroll
            for (int d = 0; d < 4; ++d) acc[a][b][d] = 0.0f;

    cp_stage(0, 0);

    for (int c = 0; c < NC; ++c) {
        cp_wait0();
        __syncthreads();
        if (c + 1 < NC) cp_stage(c + 1, (c + 1) & 1);

        const uint32_t st = sb + (c & 1) * STG;
        const uint32_t stB = st + 2 * A_T;
#pragma unroll
        for (int ks = 0; ks < 2; ++ks) {
            uint32_t bhi[2][4], blo[2][4];
#pragma unroll
            for (int ntp = 0; ntp < 2; ++ntp) {
                const uint32_t off = sw64((wn + ntp * 16 + ((lane >> 4) << 3) +
                                           (lane & 7)) * 64 +
                                          ks * 32 + ((lane >> 3) & 1) * 16);
                ldm_x4(bhi[ntp], stB + off);
                ldm_x4(blo[ntp], stB + B_T + off);
            }
#pragma unroll
            for (int mt = 0; mt < 4; ++mt) {
                uint32_t ahi[4], alo[4];
                const uint32_t off = sw64((mt * 16 + (lane & 15)) * 64 +
                                          ks * 32 + (lane >> 4) * 16);
                ldm_x4(ahi, st + off);
                ldm_x4(alo, st + A_T + off);
#pragma unroll
                for (int nt = 0; nt < 4; ++nt) {
                    const int p = nt >> 1, q = (nt & 1) * 2;
                    mma_bf16(acc[mt][nt], ahi, bhi[p][q], bhi[p][q + 1]);
                    mma_bf16(acc[mt][nt], ahi, blo[p][q], blo[p][q + 1]);
                    mma_bf16(acc[mt][nt], alo, bhi[p][q], bhi[p][q + 1]);
                }
            }
        }
        __syncthreads();
    }

    // Epilogue (bf16 hi/lo or fp32)
    if (gb.Yf[z]) {
        float* __restrict__ Y = gb.Yf[z];
#pragma unroll
        for (int mt = 0; mt < 4; ++mt) {
            const int row = m0 + mt * 16 + (lane >> 2);
#pragma unroll
            for (int nt = 0; nt < 4; ++nt) {
                const int col = n0 + wn + nt * 8 + (lane & 3) * 2;
                const float b0v = __ldg(&bias[col]);
                const float b1v = __ldg(&bias[col + 1]);
                *(float2*)(Y + (size_t)row * N + col) =
                    make_float2(acc[mt][nt][0] + b0v, acc[mt][nt][1] + b1v);
                *(float2*)(Y + (size_t)(row + 8) * N + col) =
                    make_float2(acc[mt][nt][2] + b0v, acc[mt][nt][3] + b1v);
            }
        }
    } else {
        __nv_bfloat16* __restrict__ Yh = gb.Yh[z];
        __nv_bfloat16* __restrict__ Yl = gb.Yl[z];
#pragma unroll
        for (int mt = 0; mt < 4; ++mt) {
            const int row = m0 + mt * 16 + (lane >> 2);
#pragma unroll
            for (int nt = 0; nt < 4; ++nt) {
                const int col = n0 + wn + nt * 8 + (lane & 3) * 2;
                const float b0v = __ldg(&bias[col]);
                const float b1v = __ldg(&bias[col + 1]);
                uint32_t hh, ll;
                pack_hilo(acc[mt][nt][0] + b0v, acc[mt][nt][1] + b1v, hh, ll);
                *(uint32_t*)(Yh + (size_t)row * N + col) = hh;
                *(uint32_t*)(Yl + (size_t)row * N + col) = ll;
                pack_hilo(acc[mt][nt][2] + b0v, acc[mt][nt][3] + b1v, hh, ll);
                *(uint32_t*)(Yh + (size_t)(row + 8) * N + col) = hh;
                *(uint32_t*)(Yl + (size_t)(row + 8) * N + col) = ll;
            }
        }
    }
}

// ===========================================================================
// GEMM variant B (O-projection, single-wave): 128x128x32, 256 threads,
// 8 warps (2Mx4N), 3-stage pipeline, single barrier/chunk.  [R12-measured]
// ===========================================================================
constexpr int TILE8K = 128 * BKC * 2;       // 8192
constexpr int STAGE_BYTES = 4 * TILE8K;     // 32768
constexpr int GEMM_SMEM_L = 3 * STAGE_BYTES + 1024;   // 99328

__global__ __launch_bounds__(256, 2) void gemm_bf16_l(GemmBatch gb,
                                                      int M, int N, int K)
{
    extern __shared__ char smraw[];
    const uint32_t sb = (smem_u32(smraw) + 1023) & ~1023u;
    const int z = blockIdx.z;
    const __nv_bfloat16* __restrict__ Ahi = gb.Ah[z];
    const __nv_bfloat16* __restrict__ Alo = gb.Al[z];
    const __nv_bfloat16* __restrict__ Bhi = gb.Bh[z];
    const __nv_bfloat16* __restrict__ Blo = gb.Bl[z];
    const float* __restrict__ bias = gb.bias[z];

    const int tid = threadIdx.x, lane = tid & 31, wid = tid >> 5;
    const int m0 = blockIdx.y * 128, n0 = blockIdx.x * 128;
    const int wm = (wid >> 2) * 64;
    const int wn = (wid & 3) * 32;

    const int lrow = tid >> 2;
    const int c16  = tid & 3;

    auto cp_stage = [&](int c, int s) {
        const int kc = c * BKC;
        const uint32_t st = sb + s * STAGE_BYTES;
#pragma unroll
        for (int i = 0; i < 2; ++i) {
            const int row = i * 64 + lrow;
            const uint32_t so = sw64(row * 64 + c16 * 16);
            const size_t ga = (size_t)(m0 + row) * K + kc + c16 * 8;
            const size_t gbo = (size_t)(n0 + row) * K + kc + c16 * 8;
            cp16(st + so,              Ahi + ga);
            cp16(st + TILE8K + so,     Alo + ga);
            cp16(st + 2 * TILE8K + so, Bhi + gbo);
            cp16(st + 3 * TILE8K + so, Blo + gbo);
        }
        cp_commit();
    };

    float acc[4][4][4];
#pragma unroll
    for (int a = 0; a < 4; ++a)
#pragma unroll
        for (int b = 0; b < 4; ++b)
#pragma unroll
            for (int d = 0; d < 4; ++d) acc[a][b][d] = 0.0f;

    cp_stage(0, 0);
    cp_stage(1, 1);

    int sr = 0, sw = 2;

    for (int c = 0; c < NC; ++c) {
        cp_wait1();
        __syncthreads();
        if (c + 2 < NC) cp_stage(c + 2, sw);
        else            cp_commit();

        const uint32_t st = sb + sr * STAGE_BYTES;
#pragma unroll
        for (int ks = 0; ks < 2; ++ks) {
            uint32_t bhi[2][4], blo[2][4];
#pragma unroll
            for (int ntp = 0; ntp < 2; ++ntp) {
                const uint32_t off = sw64((wn + ntp * 16 + ((lane >> 4) << 3) +
                                           (lane & 7)) * 64 +
                                          ks * 32 + ((lane >> 3) & 1) * 16);
                ldm_x4(bhi[ntp], st + 2 * TILE8K + off);
                ldm_x4(blo[ntp], st + 3 * TILE8K + off);
            }
#pragma unroll
            for (int mt = 0; mt < 4; ++mt) {
                uint32_t ahi[4], alo[4];
                const uint32_t off = sw64((wm + mt * 16 + (lane & 15)) * 64 +
                                          ks * 32 + (lane >> 4) * 16);
                ldm_x4(ahi, st + off);
                ldm_x4(alo, st + TILE8K + off);
#pragma unroll
                for (int nt = 0; nt < 4; ++nt) {
                    const int p = nt >> 1, q = (nt & 1) * 2;
                    mma_bf16(acc[mt][nt], ahi, bhi[p][q], bhi[p][q + 1]);
                    mma_bf16(acc[mt][nt], ahi, blo[p][q], blo[p][q + 1]);
                    mma_bf16(acc[mt][nt], alo, bhi[p][q], bhi[p][q + 1]);
                }
            }
        }
        sr = (sr == 2) ? 0 : sr + 1;
        sw = (sw == 2) ? 0 : sw + 1;
    }

    // Epilogue
    if (gb.Yf[z]) {
        float* __restrict__ Y = gb.Yf[z];
#pragma unroll
        for (int mt = 0; mt < 4; ++mt) {
            const int row = m0 + wm + mt * 16 + (lane >> 2);
#pragma unroll
            for (int nt = 0; nt < 4; ++nt) {
                const int col = n0 + wn + nt * 8 + (lane & 3) * 2;
                const float b0v = __ldg(&bias[col]);
                const float b1v = __ldg(&bias[col + 1]);
                *(float2*)(Y + (size_t)row * N + col) =
                    make_float2(acc[mt][nt][0] + b0v, acc[mt][nt][1] + b1v);
                *(float2*)(Y + (size_t)(row + 8) * N + col) =
                    make_float2(acc[mt][nt][2] + b0v, acc[mt][nt][3] + b1v);
            }
        }
    } else {
        __nv_bfloat16* __restrict__ Yh = gb.Yh[z];
        __nv_bfloat16* __restrict__ Yl = gb.Yl[z];
#pragma unroll
        for (int mt = 0; mt < 4; ++mt) {
            const int row = m0 + wm + mt * 16 + (lane >> 2);
#pragma unroll
            for (int nt = 0; nt < 4; ++nt) {
                const int col = n0 + wn + nt * 8 + (lane & 3) * 2;
                const float b0v = __ldg(&bias[col]);
                const float b1v = __ldg(&bias[col + 1]);
                uint32_t hh, ll;
                pack_hilo(acc[mt][nt][0] + b0v, acc[mt][nt][1] + b1v, hh, ll);
                *(uint32_t*)(Yh + (size_t)row * N + col) = hh;
                *(uint32_t*)(Yl + (size_t)row * N + col) = ll;
                pack_hilo(acc[mt][nt][2] + b0v, acc[mt][nt][3] + b1v, hh, ll);
                *(uint32_t*)(Yh + (size_t)(row + 8) * N + col) = hh;
                *(uint32_t*)(Yl + (size_t)(row + 8) * N + col) = ll;
            }
        }
    }
}

// ===========================================================================
// Tensor-core flash attention — R13-validated: 64q/128thr, 2-stage KV,
// Q fragments loaded directly from global, 3 CTAs/SM.
// ===========================================================================
constexpr int ATT_SMEM = 1024 + 2 * 32768;   // 66560

__global__ __launch_bounds__(128, 3) void attn_tc(
    const __nv_bfloat16* __restrict__ qh_, const __nv_bfloat16* __restrict__ ql_,
    const __nv_bfloat16* __restrict__ kh_, const __nv_bfloat16* __restrict__ kl_,
    const __nv_bfloat16* __restrict__ vh_, const __nv_bfloat16* __restrict__ vl_,
    __nv_bfloat16* __restrict__ ohi, __nv_bfloat16* __restrict__ olo)
{
    extern __shared__ char smraw[];
    const uint32_t sb = (smem_u32(smraw) + 1023) & ~1023u;
    const int tid = threadIdx.x, lane = tid & 31, wid = tid >> 5;
    const int qt = blockIdx.x, h = blockIdx.y, b = blockIdx.z;
    const size_t bt = (size_t)b * S_LEN;

    auto cp_kv = [&](int kt, int s) {
        const uint32_t st = sb + s * 32768;
        const int row = tid >> 3, c = tid & 7;
        const size_t g0 = (bt + (size_t)kt * 64) * D_MODEL + h * DKH + c * 8;
#pragma unroll
        for (int it = 0; it < 4; ++it) {
            const int r = it * 16 + row;
            const uint32_t so = sw128(r * 128 + c * 16);
            const size_t g = g0 + (size_t)r * D_MODEL;
            cp16(st + so,         kh_ + g);
            cp16(st + 8192 + so,  kl_ + g);
            cp16(st + 16384 + so, vh_ + g);
            cp16(st + 24576 + so, vl_ + g);
        }
        cp_commit();
    };

    cp_kv(0, 0);
    cp_kv(1, 1);

    // ---- Q fragments: direct global loads in MMA A-fragment layout ----
    uint32_t qfh[4][4], qfl[4][4];
    {
        const int qrow = qt * 64 + wid * 16 + (lane >> 2);
        const size_t base = (bt + qrow) * D_MODEL + h * DKH + (lane & 3) * 2;
        const size_t base8 = base + (size_t)8 * D_MODEL;
#pragma unroll
        for (int ks = 0; ks < 4; ++ks) {
            const int kofs = ks * 16;
            qfh[ks][0] = *(const uint32_t*)(qh_ + base  + kofs);
            qfh[ks][1] = *(const uint32_t*)(qh_ + base8 + kofs);
            qfh[ks][2] = *(const uint32_t*)(qh_ + base  + kofs + 8);
            qfh[ks][3] = *(const uint32_t*)(qh_ + base8 + kofs + 8);
            qfl[ks][0] = *(const uint32_t*)(ql_ + base  + kofs);
            qfl[ks][1] = *(const uint32_t*)(ql_ + base8 + kofs);
            qfl[ks][2] = *(const uint32_t*)(ql_ + base  + kofs + 8);
            qfl[ks][3] = *(const uint32_t*)(ql_ + base8 + kofs + 8);
        }
    }

    float s[8][4], out[8][4];
    float m0 = -1e30f, m1 = -1e30f, l0 = 0.0f, l1 = 0.0f;
#pragma unroll
    for (int nt = 0; nt < 8; ++nt)
#pragma unroll
        for (int v = 0; v < 4; ++v) out[nt][v] = 0.0f;

    constexpr float SC = 0.18033688f;   // 0.125 * log2(e)

    for (int kt = 0; kt < S_LEN / 64; ++kt) {
        cp_wait1();
        __syncthreads();

        const uint32_t KH = sb + (kt & 1) * 32768;
        const uint32_t KL = KH + 8192, VH = KH + 16384, VL = KH + 24576;

        // ---- scores S = Q.K^T (hi/lo 3-MMA) ----
#pragma unroll
        for (int nt = 0; nt < 8; ++nt)
#pragma unroll
            for (int v = 0; v < 4; ++v) s[nt][v] = 0.0f;

#pragma unroll
        for (int ntp = 0; ntp < 4; ++ntp) {
            const uint32_t rb = (ntp * 16 + ((lane >> 4) << 3) + (lane & 7)) * 128;
#pragma unroll
            for (int ks = 0; ks < 4; ++ks) {
                const uint32_t off = sw128(rb + ks * 32 + ((lane >> 3) & 1) * 16);
                uint32_t bh[4], bl[4];
                ldm_x4(bh, KH + off);
                ldm_x4(bl, KL + off);
                mma_bf16(s[2 * ntp],     qfh[ks], bh[0], bh[1]);
                mma_bf16(s[2 * ntp],     qfh[ks], bl[0], bl[1]);
                mma_bf16(s[2 * ntp],     qfl[ks], bh[0], bh[1]);
                mma_bf16(s[2 * ntp + 1], qfh[ks], bh[2], bh[3]);
                mma_bf16(s[2 * ntp + 1], qfh[ks], bl[2], bl[3]);
                mma_bf16(s[2 * ntp + 1], qfl[ks], bh[2], bh[3]);
            }
        }

        // ---- online softmax (exp2 domain) ----
        float mx0 = -1e30f, mx1 = -1e30f;
#pragma unroll
        for (int nt = 0; nt < 8; ++nt) {
            s[nt][0] *= SC; s[nt][1] *= SC; s[nt][2] *= SC; s[nt][3] *= SC;
            mx0 = fmaxf(mx0, fmaxf(s[nt][0], s[nt][1]));
            mx1 = fmaxf(mx1, fmaxf(s[nt][2], s[nt][3]));
        }
        mx0 = fmaxf(mx0, __shfl_xor_sync(0xffffffffu, mx0, 1));
        mx0 = fmaxf(mx0, __shfl_xor_sync(0xffffffffu, mx0, 2));
        mx1 = fmaxf(mx1, __shfl_xor_sync(0xffffffffu, mx1, 1));
        mx1 = fmaxf(mx1, __shfl_xor_sync(0xffffffffu, mx1, 2));
        const float nm0 = fmaxf(m0, mx0), nm1 = fmaxf(m1, mx1);
        const float a0 = ex2(m0 - nm0), a1 = ex2(m1 - nm1);
        m0 = nm0; m1 = nm1;
        float rs0 = 0.0f, rs1 = 0.0f;
#pragma unroll
        for (int nt = 0; nt < 8; ++nt) {
            s[nt][0] = ex2(s[nt][0] - m0);
            s[nt][1] = ex2(s[nt][1] - m0);
            s[nt][2] = ex2(s[nt][2] - m1);
            s[nt][3] = ex2(s[nt][3] - m1);
            rs0 += s[nt][0] + s[nt][1];
            rs1 += s[nt][2] + s[nt][3];
            out[nt][0] *= a0; out[nt][1] *= a0;
            out[nt][2] *= a1; out[nt][3] *= a1;
        }
        rs0 += __shfl_xor_sync(0xffffffffu, rs0, 1);
        rs0 += __shfl_xor_sync(0xffffffffu, rs0, 2);
        rs1 += __shfl_xor_sync(0xffffffffu, rs1, 1);
        rs1 += __shfl_xor_sync(0xffffffffu, rs1, 2);
        l0 = l0 * a0 + rs0;
        l1 = l1 * a1 + rs1;

        // ---- PV: out += P.V ----
#pragma unroll
        for (int ks = 0; ks < 4; ++ks) {
            uint32_t ph[4], pl[4];
            pack_hilo(s[2 * ks][0],     s[2 * ks][1],     ph[0], pl[0]);
            pack_hilo(s[2 * ks][2],     s[2 * ks][3],     ph[1], pl[1]);
            pack_hilo(s[2 * ks + 1][0], s[2 * ks + 1][1], ph[2], pl[2]);
            pack_hilo(s[2 * ks + 1][2], s[2 * ks + 1][3], ph[3], pl[3]);
            const uint32_t vrow = (ks * 16 + ((lane >> 3) & 1) * 8 + (lane & 7)) * 128;
#pragma unroll
            for (int np = 0; np < 4; ++np) {
                const uint32_t off = sw128(vrow + np * 32 + (lane >> 4) * 16);
                uint32_t vh4[4], vl4[4];
                ldm_x4_t(vh4, VH + off);
                ldm_x4_t(vl4, VL + off);
                mma_bf16(out[2 * np],     ph, vh4[0], vh4[1]);
                mma_bf16(out[2 * np],     ph, vl4[0], vl4[1]);
                mma_bf16(out[2 * np],     pl, vh4[0], vh4[1]);
                mma_bf16(out[2 * np + 1], ph, vh4[2], vh4[3]);
                mma_bf16(out[2 * np + 1], ph, vl4[2], vl4[3]);
                mma_bf16(out[2 * np + 1], pl, vh4[2], vh4[3]);
            }
        }

        __syncthreads();
        if (kt + 2 < S_LEN / 64) cp_kv(kt + 2, kt & 1);
        else cp_commit();
    }

    // ---- epilogue: normalize, emit bf16 hi/lo for the O-projection ----
    const float i0 = 1.0f / l0, i1 = 1.0f / l1;
    const int r0 = qt * 64 + wid * 16 + (lane >> 2);
    const size_t t0 = (bt + r0) * D_MODEL;
    const size_t t1 = t0 + 8 * D_MODEL;
#pragma unroll
    for (int nt = 0; nt < 8; ++nt) {
        const int col = h * DKH + nt * 8 + (lane & 3) * 2;
        uint32_t hh, ll;
        pack_hilo(out[nt][0] * i0, out[nt][1] * i0, hh, ll);
        *(uint32_t*)(ohi + t0 + col) = hh;
        *(uint32_t*)(olo + t0 + col) = ll;
        pack_hilo(out[nt][2] * i1, out[nt][3] * i1, hh, ll);
        *(uint32_t*)(ohi + t1 + col) = hh;
        *(uint32_t*)(olo + t1 + col) = ll;
    }
}

// ===========================================================================
// kernel_launch: Q K V Wq bq Wk bk Wv bv Wo bo ; output float32
// ===========================================================================
extern "C" void kernel_launch(void* const* d_in, const int* in_sizes, int n_in,
                              void* d_out, int out_size)
{
    const float* Q  = (const float*)d_in[0];
    const float* K  = (const float*)d_in[1];
    const float* V  = (const float*)d_in[2];
    const float* Wq = (const float*)d_in[3];
    const float* bq = (const float*)d_in[4];
    const float* Wk = (const float*)d_in[5];
    const float* bk = (const float*)d_in[6];
    const float* Wv = (const float*)d_in[7];
    const float* bv = (const float*)d_in[8];
    const float* Wo = (const float*)d_in[9];
    const float* bo = (const float*)d_in[10];
    float* out = (float*)d_out;

    __nv_bfloat16 *xhi, *xlo, *kih, *kil, *vih, *vil;
    __nv_bfloat16 *wqh, *wql, *wkh, *wkl, *wvh, *wvl, *woh, *wol;
    __nv_bfloat16 *qhi, *qlo, *khi, *klo, *vhi, *vlo;
    cudaGetSymbolAddress((void**)&xhi, g_xhi);
    cudaGetSymbolAddress((void**)&xlo, g_xlo);
    cudaGetSymbolAddress((void**)&kih, g_khi_in);
    cudaGetSymbolAddress((void**)&kil, g_klo_in);
    cudaGetSymbolAddress((void**)&vih, g_vhi_in);
    cudaGetSymbolAddress((void**)&vil, g_vlo_in);
    cudaGetSymbolAddress((void**)&wqh, g_wqhi);
    cudaGetSymbolAddress((void**)&wql, g_wqlo);
    cudaGetSymbolAddress((void**)&wkh, g_wkhi);
    cudaGetSymbolAddress((void**)&wkl, g_wklo);
    cudaGetSymbolAddress((void**)&wvh, g_wvhi);
    cudaGetSymbolAddress((void**)&wvl, g_wvlo);
    cudaGetSymbolAddress((void**)&woh, g_wohi);
    cudaGetSymbolAddress((void**)&wol, g_wolo);
    cudaGetSymbolAddress((void**)&qhi, g_qhi);
    cudaGetSymbolAddress((void**)&qlo, g_qlo);
    cudaGetSymbolAddress((void**)&khi, g_khi);
    cudaGetSymbolAddress((void**)&klo, g_klo);
    cudaGetSymbolAddress((void**)&vhi, g_vhi);
    cudaGetSymbolAddress((void**)&vlo, g_vlo);

    cudaFuncSetAttribute(gemm_bf16_s,
                         cudaFuncAttributeMaxDynamicSharedMemorySize, GEMM_SMEM_S);
    cudaFuncSetAttribute(gemm_bf16_l,
                         cudaFuncAttributeMaxDynamicSharedMemorySize, GEMM_SMEM_L);
    cudaFuncSetAttribute(attn_tc,
                         cudaFuncAttributeMaxDynamicSharedMemorySize, ATT_SMEM);

    const int nX4 = NTOK * D_MODEL / 4;      // 1,048,576
    const int nW4 = D_MODEL * D_MODEL / 4;   // 262,144

    // --- single batched conversion (MLP=4): inputs + 4 weights ---
    CvtBatch cb;
    cb.in[0] = Q;  cb.hi[0] = xhi; cb.lo[0] = xlo; cb.n4[0] = nX4;
    cb.in[1] = K;  cb.hi[1] = kih; cb.lo[1] = kil; cb.n4[1] = nX4;
    cb.in[2] = V;  cb.hi[2] = vih; cb.lo[2] = vil; cb.n4[2] = nX4;
    cb.in[3] = Wq; cb.hi[3] = wqh; cb.lo[3] = wql; cb.n4[3] = nW4;
    cb.in[4] = Wk; cb.hi[4] = wkh; cb.lo[4] = wkl; cb.n4[4] = nW4;
    cb.in[5] = Wv; cb.hi[5] = wvh; cb.lo[5] = wvl; cb.n4[5] = nW4;
    cb.in[6] = Wo; cb.hi[6] = woh; cb.lo[6] = wol; cb.n4[6] = nW4;
    cvt_batch_kernel<<<dim3(nX4 / 1024, 7), 256>>>(cb);

    // --- fused QKV projections: small-tile variant (multi-wave optimal) ---
    GemmBatch gq;
    gq.Ah[0] = xhi; gq.Al[0] = xlo; gq.Bh[0] = wqh; gq.Bl[0] = wql;
    gq.bias[0] = bq; gq.Yf[0] = nullptr; gq.Yh[0] = qhi; gq.Yl[0] = qlo;
    gq.Ah[1] = kih; gq.Al[1] = kil; gq.Bh[1] = wkh; gq.Bl[1] = wkl;
    gq.bias[1] = bk; gq.Yf[1] = nullptr; gq.Yh[1] = khi; gq.Yl[1] = klo;
    gq.Ah[2] = vih; gq.Al[2] = vil; gq.Bh[2] = wvh; gq.Bl[2] = wvl;
    gq.bias[2] = bv; gq.Yf[2] = nullptr; gq.Yh[2] = vhi; gq.Yl[2] = vlo;
    dim3 ggrid(D_MODEL / 128, NTOK / 64, 3);     // (8, 64, 3)
    gemm_bf16_s<<<ggrid, 128, GEMM_SMEM_S>>>(gq, NTOK, D_MODEL, D_MODEL);

    // --- attention: 64-query CTAs, 3 CTAs/SM ---
    dim3 agrid(S_LEN / 64, NHEAD, B_SZ);         // (32, 16, 2)
    attn_tc<<<agrid, 128, ATT_SMEM>>>(qhi, qlo, khi, klo, vhi, vlo, xhi, xlo);

    // --- output projection: large-tile variant (single-wave optimal) ---
    GemmBatch go;
    go.Ah[0] = xhi; go.Al[0] = xlo; go.Bh[0] = woh; go.Bl[0] = wol;
    go.bias[0] = bo; go.Yf[0] = out; go.Yh[0] = nullptr; go.Yl[0] = nullptr;
    go.Ah[1] = go.Ah[2] = xhi; go.Al[1] = go.Al[2] = xlo;
    go.Bh[1] = go.Bh[2] = woh; go.Bl[1] = go.Bl[2] = wol;
    go.bias[1] = go.bias[2] = bo;
    go.Yf[1] = go.Yf[2] = out;
    go.Yh[1] = go.Yh[2] = nullptr; go.Yl[1] = go.Yl[2] = nullptr;
    dim3 ogrid(D_MODEL / 128, NTOK / 128, 1);    // (8, 32, 1)
    gemm_bf16_l<<<ogrid, 256, GEMM_SMEM_L>>>(go, NTOK, D_MODEL, D_MODEL);
}